// round 16
// baseline (speedup 1.0000x reference)
#include <cuda_runtime.h>
#include <math.h>

#define NC 36
#define WPB 8   // dpp tokens (warps) per block

// Scratch (no allocation allowed -> __device__ globals)
__device__ __align__(16) float g_q[24 * 512 * 64];
__device__ __align__(16) float g_k[24 * 512 * 64];
__device__ __align__(16) float g_v[24 * 512 * 64];
__device__ __align__(16) float g_sim[(size_t)24 * 512 * 512];
__device__ __align__(16) float g_ymid[1024 * 768];
__device__ __align__(16) float g_part[(size_t)6 * 1024 * 768];

// ---- packed f32x2 helpers (ptxas never emits FFMA2 from C++; PTX only) ----
__device__ __forceinline__ unsigned long long dup2(float x) {
    unsigned long long r;
    asm("mov.b64 %0, {%1, %1};" : "=l"(r) : "f"(x));
    return r;
}
__device__ __forceinline__ void fma2(unsigned long long& d,
                                     unsigned long long a,
                                     unsigned long long b) {
    asm("fma.rn.f32x2 %0, %1, %2, %0;" : "+l"(d) : "l"(a), "l"(b));
}
__device__ __forceinline__ float2 unpk(unsigned long long v) {
    float2 f;
    asm("mov.b64 {%0, %1}, %2;" : "=f"(f.x), "=f"(f.y) : "l"(v));
    return f;
}

// ---------------------------------------------------------------------------
// Kernel 1: qkv = x @ W_attn^T + b_attn, scattered into per-head q/k/v layout.
// 128x128 tile, BK=16, 256 threads, 8x8 micro-tile, double-buffered smem,
// packed fma.rn.f32x2 inner loop (2 FMA / fma-pipe slot).
// ---------------------------------------------------------------------------
__global__ __launch_bounds__(256, 2)
void qkv_gemm(const float* __restrict__ X, const float* __restrict__ W,
              const float* __restrict__ bias) {
    __shared__ float As[2][16][132];
    __shared__ float Bs[2][16][132];
    const int tid = threadIdx.x;
    const int tx = tid & 15, ty = tid >> 4;
    const int row0 = blockIdx.y * 128;
    const int col0 = blockIdx.x * 128;
    const int lr = tid >> 2;          // 0..63
    const int lk = (tid & 3) * 4;     // 0,4,8,12
    unsigned long long accp[8][4] = {};   // 8 rows x 4 col-pairs

    const float* pa0 = X + (size_t)(row0 + lr) * 768 + lk;
    const float* pa1 = X + (size_t)(row0 + lr + 64) * 768 + lk;
    const float* pb0 = W + (size_t)(col0 + lr) * 768 + lk;
    const float* pb1 = W + (size_t)(col0 + lr + 64) * 768 + lk;

    float4 fa0 = *(const float4*)pa0;
    float4 fa1 = *(const float4*)pa1;
    float4 fb0 = *(const float4*)pb0;
    float4 fb1 = *(const float4*)pb1;
    As[0][lk + 0][lr] = fa0.x; As[0][lk + 1][lr] = fa0.y;
    As[0][lk + 2][lr] = fa0.z; As[0][lk + 3][lr] = fa0.w;
    As[0][lk + 0][lr + 64] = fa1.x; As[0][lk + 1][lr + 64] = fa1.y;
    As[0][lk + 2][lr + 64] = fa1.z; As[0][lk + 3][lr + 64] = fa1.w;
    Bs[0][lk + 0][lr] = fb0.x; Bs[0][lk + 1][lr] = fb0.y;
    Bs[0][lk + 2][lr] = fb0.z; Bs[0][lk + 3][lr] = fb0.w;
    Bs[0][lk + 0][lr + 64] = fb1.x; Bs[0][lk + 1][lr + 64] = fb1.y;
    Bs[0][lk + 2][lr + 64] = fb1.z; Bs[0][lk + 3][lr + 64] = fb1.w;
    __syncthreads();

    const int NT = 768 / 16;
    for (int t = 0; t < NT; t++) {
        const int buf = t & 1;
        if (t < NT - 1) {
            int off = (t + 1) * 16;
            fa0 = *(const float4*)(pa0 + off);
            fa1 = *(const float4*)(pa1 + off);
            fb0 = *(const float4*)(pb0 + off);
            fb1 = *(const float4*)(pb1 + off);
        }
#pragma unroll
        for (int kk = 0; kk < 16; kk++) {
            float4 a0 = *(const float4*)&As[buf][kk][ty * 8];
            float4 a1 = *(const float4*)&As[buf][kk][ty * 8 + 4];
            ulonglong2 bl = *(const ulonglong2*)&Bs[buf][kk][tx * 8];
            ulonglong2 bh = *(const ulonglong2*)&Bs[buf][kk][tx * 8 + 4];
            unsigned long long bp0 = bl.x, bp1 = bl.y, bp2 = bh.x, bp3 = bh.y;
            float av[8] = {a0.x, a0.y, a0.z, a0.w, a1.x, a1.y, a1.z, a1.w};
#pragma unroll
            for (int r = 0; r < 8; r++) {
                unsigned long long ad = dup2(av[r]);
                fma2(accp[r][0], ad, bp0);
                fma2(accp[r][1], ad, bp1);
                fma2(accp[r][2], ad, bp2);
                fma2(accp[r][3], ad, bp3);
            }
        }
        if (t < NT - 1) {
            const int nb = buf ^ 1;
            As[nb][lk + 0][lr] = fa0.x; As[nb][lk + 1][lr] = fa0.y;
            As[nb][lk + 2][lr] = fa0.z; As[nb][lk + 3][lr] = fa0.w;
            As[nb][lk + 0][lr + 64] = fa1.x; As[nb][lk + 1][lr + 64] = fa1.y;
            As[nb][lk + 2][lr + 64] = fa1.z; As[nb][lk + 3][lr + 64] = fa1.w;
            Bs[nb][lk + 0][lr] = fb0.x; Bs[nb][lk + 1][lr] = fb0.y;
            Bs[nb][lk + 2][lr] = fb0.z; Bs[nb][lk + 3][lr] = fb0.w;
            Bs[nb][lk + 0][lr + 64] = fb1.x; Bs[nb][lk + 1][lr + 64] = fb1.y;
            Bs[nb][lk + 2][lr + 64] = fb1.z; Bs[nb][lk + 3][lr + 64] = fb1.w;
            __syncthreads();
        }
    }

    // Epilogue: bias + scatter into per-head q/k/v layout.
    const int j0 = col0 + tx * 8;
    float bb[8];
    *(float4*)&bb[0] = *(const float4*)(bias + j0);
    *(float4*)&bb[4] = *(const float4*)(bias + j0 + 4);
    const int which = j0 / 768;
    const int cc0 = j0 % 768;
    const int head = cc0 >> 6;
    const int d0 = cc0 & 63;
    float* dstbase = (which == 0) ? g_q : (which == 1) ? g_k : g_v;
#pragma unroll
    for (int r = 0; r < 8; r++) {
        int i = row0 + ty * 8 + r;
        int b_ = i >> 9, t = i & 511;
        int bh = b_ * 12 + head;
        float* p = dstbase + ((size_t)(bh * 512 + t)) * 64 + d0;
        float2 c0 = unpk(accp[r][0]), c1 = unpk(accp[r][1]);
        float2 c2 = unpk(accp[r][2]), c3 = unpk(accp[r][3]);
        *(float4*)p = make_float4(c0.x + bb[0], c0.y + bb[1],
                                  c1.x + bb[2], c1.y + bb[3]);
        *(float4*)(p + 4) = make_float4(c2.x + bb[4], c2.y + bb[5],
                                        c3.x + bb[6], c3.y + bb[7]);
    }
}

// ---------------------------------------------------------------------------
// Kernel 2: per-head similarity S[h][i][j] = q[h][i].k[h][j] (j<=i, else -inf)
// Transposed smem ([d][token]) so column pairs are contiguous -> f32x2.
// ---------------------------------------------------------------------------
__global__ void sim_kernel() {
    int h = blockIdx.z;
    int ti = blockIdx.y, tj = blockIdx.x;
    if (tj > ti) return;   // above-diagonal tiles never read
    __shared__ float Qs[64][68];   // [d][token], 68 stride keeps 16B align
    __shared__ float Ks[64][68];
    int tid = threadIdx.x;
    const int lr = tid >> 2;          // token 0..63
    const int lk = (tid & 3) * 4;     // d base 0,4,8,12
#pragma unroll
    for (int e = 0; e < 4; e++) {
        int d = lk + e * 16;
        float4 fq = *(const float4*)(g_q + ((size_t)(h * 512) + ti * 64 + lr) * 64 + d);
        Qs[d + 0][lr] = fq.x; Qs[d + 1][lr] = fq.y;
        Qs[d + 2][lr] = fq.z; Qs[d + 3][lr] = fq.w;
        float4 fk = *(const float4*)(g_k + ((size_t)(h * 512) + tj * 64 + lr) * 64 + d);
        Ks[d + 0][lr] = fk.x; Ks[d + 1][lr] = fk.y;
        Ks[d + 2][lr] = fk.z; Ks[d + 3][lr] = fk.w;
    }
    __syncthreads();
    int tx = tid & 15, ty = tid >> 4;
    unsigned long long accp[4][2] = {};
#pragma unroll 8
    for (int d = 0; d < 64; d++) {
        float4 a = *(const float4*)&Qs[d][ty * 4];
        ulonglong2 b = *(const ulonglong2*)&Ks[d][tx * 4];
        float av[4] = {a.x, a.y, a.z, a.w};
#pragma unroll
        for (int r = 0; r < 4; r++) {
            unsigned long long ad = dup2(av[r]);
            fma2(accp[r][0], ad, b.x);
            fma2(accp[r][1], ad, b.y);
        }
    }
#pragma unroll
    for (int r = 0; r < 4; r++) {
        int i = ti * 64 + ty * 4 + r;
        float2 c0 = unpk(accp[r][0]);
        float2 c1 = unpk(accp[r][1]);
        float vv[4] = {c0.x, c0.y, c1.x, c1.y};
#pragma unroll
        for (int c = 0; c < 4; c++) {
            int j = tj * 64 + tx * 4 + c;
            g_sim[((size_t)h * 512 + i) * 512 + j] = (j <= i) ? vv[c] : -INFINITY;
        }
    }
}

// ---------------------------------------------------------------------------
// Kernel 3: DPP, one WARP per (head, token). 8 tokens per block, no block
// barriers at all — everything is warp-local (__syncwarp / shuffles).
// ---------------------------------------------------------------------------
__global__ __launch_bounds__(256)
void dpp_kernel() {
    const int w    = threadIdx.x >> 5;           // warp slot = token slot
    const int lane = threadIdx.x & 31;
    const int i    = blockIdx.x * WPB + w;       // token 0..511
    const int bh   = blockIdx.y;                 // 0..23

    __shared__ float s_sim[WPB][512];
    __shared__ float kc[WPB][9][65];             // pad 65 -> conflict-free gram
    __shared__ float G[WPB][9][9];
    __shared__ float sc[WPB][NC];
    __shared__ float sw[WPB][NC][3];
    __shared__ unsigned char sg[WPB][NC][3];
    __shared__ float sprob[WPB][NC];
    __shared__ float coeff[WPB][9];
    __shared__ int   topidx[WPB][8];
    __shared__ float topval[WPB][8];

    const float* simrow = g_sim + ((size_t)bh * 512 + i) * 512;
#pragma unroll
    for (int e = 0; e < 16; e++) {
        int j = lane + e * 32;
        s_sim[w][j] = (j <= i) ? simrow[j] : -INFINITY;
    }
    __syncwarp();

    const float simi = s_sim[w][i];   // diagonal, always valid

    // ---- iterative top-8 argmax (tie -> lower index) ----
    for (int it = 0; it < 8; it++) {
        float bv = -INFINITY; int bi = 0x7fffffff;
#pragma unroll
        for (int e = 0; e < 16; e++) {
            int j = lane + e * 32;
            float v = s_sim[w][j];
            if (v > bv || (v == bv && j < bi)) { bv = v; bi = j; }
        }
#pragma unroll
        for (int off = 16; off > 0; off >>= 1) {
            float ov = __shfl_down_sync(0xffffffffu, bv, off);
            int   oi = __shfl_down_sync(0xffffffffu, bi, off);
            if (ov > bv || (ov == bv && oi < bi)) { bv = ov; bi = oi; }
        }
        bi = __shfl_sync(0xffffffffu, bi, 0);
        bv = __shfl_sync(0xffffffffu, bv, 0);
        if (lane == 0) { topidx[w][it] = bi; topval[w][it] = bv; }
        s_sim[w][bi] = -INFINITY;    // all lanes write same value
        __syncwarp();
    }

    const int n_cand = (i + 1 < 8) ? (i + 1) : 8;

    // ---- load 9 candidate k-vectors ----
    for (int idx = lane; idx < 9 * 64; idx += 32) {
        int m = idx >> 6, d = idx & 63;
        int src = (m == 0) ? i : topidx[w][m - 1];
        kc[w][m][d] = g_k[((size_t)bh * 512 + src) * 64 + d];
    }
    __syncwarp();

    // ---- 9x9 Gram (45 unique dots spread over lanes) ----
    for (int p = lane; p < 45; p += 32) {
        int a = 0, t = p;
        while (t >= 9 - a) { t -= 9 - a; a++; }
        int b = a + t;
        float dot = 0.f;
#pragma unroll 16
        for (int d = 0; d < 64; d++) dot = fmaf(kc[w][a][d], kc[w][b][d], dot);
        G[w][a][b] = dot;
        G[w][b][a] = dot;
    }
    __syncwarp();

    // ---- 36 combos: det, score, subset softmax weights ----
    for (int c = lane; c < NC; c += 32) {
        int s0, s1 = -1, n;
        if (c < 8) { s0 = c; n = 2; }
        else {
            int cc = c - 8, a = 0;
            while (cc >= 7 - a) { cc -= 7 - a; a++; }
            s0 = a; s1 = a + 1 + cc; n = 3;
        }
        bool valid = (s0 < n_cand) && (topidx[w][s0] != i);
        if (n == 3) valid = valid && (s1 < n_cand) && (topidx[w][s1] != i);

        int g1 = s0 + 1;
        int g2 = (n == 3) ? s1 + 1 : 0;
        float w0 = 0.f, w1 = 0.f, w2 = 0.f;
        float score = -INFINITY;
        if (valid) {
            float a00 = G[w][0][0], a01 = G[w][0][g1], a11 = G[w][g1][g1];
            float det;
            if (n == 2) {
                det = a00 * a11 - a01 * a01;
            } else {
                float a02 = G[w][0][g2], a12 = G[w][g1][g2], a22 = G[w][g2][g2];
                det = a00 * (a11 * a22 - a12 * a12)
                    - a01 * (a01 * a22 - a12 * a02)
                    + a02 * (a01 * a12 - a11 * a02);
            }
            score = logf(det + 1e-6f) / (float)n;
            float d0 = simi * 0.125f;
            float d1 = topval[w][s0] * 0.125f;
            float d2 = (n == 3) ? topval[w][s1] * 0.125f : -INFINITY;
            float m = fmaxf(d0, d1);
            if (n == 3) m = fmaxf(m, d2);
            float e0 = expf(d0 - m), e1 = expf(d1 - m);
            float e2 = (n == 3) ? expf(d2 - m) : 0.f;
            float inv = 1.f / (e0 + e1 + e2);
            w0 = e0 * inv; w1 = e1 * inv; w2 = e2 * inv;
        }
        sc[w][c] = score;
        sw[w][c][0] = w0; sw[w][c][1] = w1; sw[w][c][2] = w2;
        sg[w][c][0] = 0;
        sg[w][c][1] = (unsigned char)g1;
        sg[w][c][2] = (unsigned char)g2;
    }
    __syncwarp();

    // ---- softmax over 36 combo scores (lane 0 serial, then broadcast) ----
    float smax = -INFINITY, sinv = 0.f;
    int hv = 0;
    if (lane == 0) {
        for (int c = 0; c < NC; c++) smax = fmaxf(smax, sc[w][c]);
        hv = (smax > -INFINITY) ? 1 : 0;
        float sum = 0.f;
        if (hv) for (int c = 0; c < NC; c++) sum += expf(sc[w][c] - smax);
        sinv = (sum > 0.f) ? 1.f / sum : 0.f;
    }
    smax = __shfl_sync(0xffffffffu, smax, 0);
    sinv = __shfl_sync(0xffffffffu, sinv, 0);
    hv   = __shfl_sync(0xffffffffu, hv, 0);

    for (int c = lane; c < NC; c += 32)
        sprob[w][c] = hv ? expf(sc[w][c] - smax) * sinv : 0.f;
    __syncwarp();

    // ---- deterministic per-candidate coefficient reduction ----
    if (lane < 9) {
        float acc = 0.f;
        for (int c = 0; c < NC; c++) {
            float p = sprob[w][c];
            if (sg[w][c][0] == lane) acc = fmaf(p, sw[w][c][0], acc);
            if (sg[w][c][1] == lane) acc = fmaf(p, sw[w][c][1], acc);
            if (sg[w][c][2] == lane) acc = fmaf(p, sw[w][c][2], acc);
        }
        coeff[w][lane] = acc;
    }
    __syncwarp();

    // ---- output: y = sum_m coeff[m] * v[idx_m] (or v[i] if no valid combo) ----
    const float* vbase = g_v + (size_t)bh * 512 * 64;
    const int b_ = bh / 12, head = bh % 12;
#pragma unroll
    for (int e = 0; e < 2; e++) {
        int d = lane + e * 32;
        float y;
        if (hv) {
            y = coeff[w][0] * vbase[i * 64 + d];
#pragma unroll
            for (int m = 0; m < 8; m++)
                y = fmaf(coeff[w][m + 1], vbase[topidx[w][m] * 64 + d], y);
        } else {
            y = vbase[i * 64 + d];
        }
        g_ymid[((size_t)(b_ * 512 + i)) * 768 + head * 64 + d] = y;
    }
}

// ---------------------------------------------------------------------------
// Kernel 4: proj partial GEMM, split-K=6, double-buffered, f32x2 inner loop.
// grid (6, 8, 6) = 288 blocks.
// ---------------------------------------------------------------------------
__global__ __launch_bounds__(256, 2)
void proj_gemm(const float* __restrict__ W) {
    __shared__ float As[2][16][132];
    __shared__ float Bs[2][16][132];
    const int tid = threadIdx.x;
    const int tx = tid & 15, ty = tid >> 4;
    const int row0 = blockIdx.y * 128;
    const int col0 = blockIdx.x * 128;
    const int kbeg = blockIdx.z * 128;
    const int lr = tid >> 2;
    const int lk = (tid & 3) * 4;
    unsigned long long accp[8][4] = {};

    const float* pa0 = g_ymid + (size_t)(row0 + lr) * 768 + kbeg + lk;
    const float* pa1 = g_ymid + (size_t)(row0 + lr + 64) * 768 + kbeg + lk;
    const float* pb0 = W + (size_t)(col0 + lr) * 768 + kbeg + lk;
    const float* pb1 = W + (size_t)(col0 + lr + 64) * 768 + kbeg + lk;

    float4 fa0 = *(const float4*)pa0;
    float4 fa1 = *(const float4*)pa1;
    float4 fb0 = *(const float4*)pb0;
    float4 fb1 = *(const float4*)pb1;
    As[0][lk + 0][lr] = fa0.x; As[0][lk + 1][lr] = fa0.y;
    As[0][lk + 2][lr] = fa0.z; As[0][lk + 3][lr] = fa0.w;
    As[0][lk + 0][lr + 64] = fa1.x; As[0][lk + 1][lr + 64] = fa1.y;
    As[0][lk + 2][lr + 64] = fa1.z; As[0][lk + 3][lr + 64] = fa1.w;
    Bs[0][lk + 0][lr] = fb0.x; Bs[0][lk + 1][lr] = fb0.y;
    Bs[0][lk + 2][lr] = fb0.z; Bs[0][lk + 3][lr] = fb0.w;
    Bs[0][lk + 0][lr + 64] = fb1.x; Bs[0][lk + 1][lr + 64] = fb1.y;
    Bs[0][lk + 2][lr + 64] = fb1.z; Bs[0][lk + 3][lr + 64] = fb1.w;
    __syncthreads();

    const int NT = 8;   // 128 / 16
    for (int t = 0; t < NT; t++) {
        const int buf = t & 1;
        if (t < NT - 1) {
            int off = (t + 1) * 16;
            fa0 = *(const float4*)(pa0 + off);
            fa1 = *(const float4*)(pa1 + off);
            fb0 = *(const float4*)(pb0 + off);
            fb1 = *(const float4*)(pb1 + off);
        }
#pragma unroll
        for (int kk = 0; kk < 16; kk++) {
            float4 a0 = *(const float4*)&As[buf][kk][ty * 8];
            float4 a1 = *(const float4*)&As[buf][kk][ty * 8 + 4];
            ulonglong2 bl = *(const ulonglong2*)&Bs[buf][kk][tx * 8];
            ulonglong2 bh = *(const ulonglong2*)&Bs[buf][kk][tx * 8 + 4];
            unsigned long long bp0 = bl.x, bp1 = bl.y, bp2 = bh.x, bp3 = bh.y;
            float av[8] = {a0.x, a0.y, a0.z, a0.w, a1.x, a1.y, a1.z, a1.w};
#pragma unroll
            for (int r = 0; r < 8; r++) {
                unsigned long long ad = dup2(av[r]);
                fma2(accp[r][0], ad, bp0);
                fma2(accp[r][1], ad, bp1);
                fma2(accp[r][2], ad, bp2);
                fma2(accp[r][3], ad, bp3);
            }
        }
        if (t < NT - 1) {
            const int nb = buf ^ 1;
            As[nb][lk + 0][lr] = fa0.x; As[nb][lk + 1][lr] = fa0.y;
            As[nb][lk + 2][lr] = fa0.z; As[nb][lk + 3][lr] = fa0.w;
            As[nb][lk + 0][lr + 64] = fa1.x; As[nb][lk + 1][lr + 64] = fa1.y;
            As[nb][lk + 2][lr + 64] = fa1.z; As[nb][lk + 3][lr + 64] = fa1.w;
            Bs[nb][lk + 0][lr] = fb0.x; Bs[nb][lk + 1][lr] = fb0.y;
            Bs[nb][lk + 2][lr] = fb0.z; Bs[nb][lk + 3][lr] = fb0.w;
            Bs[nb][lk + 0][lr + 64] = fb1.x; Bs[nb][lk + 1][lr + 64] = fb1.y;
            Bs[nb][lk + 2][lr + 64] = fb1.z; Bs[nb][lk + 3][lr + 64] = fb1.w;
            __syncthreads();
        }
    }

    float* part = g_part + (size_t)blockIdx.z * (1024 * 768);
    const int j0 = col0 + tx * 8;
#pragma unroll
    for (int r = 0; r < 8; r++) {
        int i = row0 + ty * 8 + r;
        float* p = part + (size_t)i * 768 + j0;
        float2 c0 = unpk(accp[r][0]), c1 = unpk(accp[r][1]);
        float2 c2 = unpk(accp[r][2]), c3 = unpk(accp[r][3]);
        *(float4*)p       = make_float4(c0.x, c0.y, c1.x, c1.y);
        *(float4*)(p + 4) = make_float4(c2.x, c2.y, c3.x, c3.y);
    }
}

// ---------------------------------------------------------------------------
// Kernel 5: reduce split-K partials + bias (deterministic fixed order).
// ---------------------------------------------------------------------------
__global__ void proj_reduce(const float* __restrict__ bias, float* __restrict__ out) {
    const int idx = blockIdx.x * 256 + threadIdx.x;   // float4 index, 196608 total
    const float4* p = (const float4*)g_part;
    float4 s = p[idx];
#pragma unroll
    for (int z = 1; z < 6; z++) {
        float4 t = p[idx + z * 196608];
        s.x += t.x; s.y += t.y; s.z += t.z; s.w += t.w;
    }
    int j = (idx * 4) % 768;
    float4 bv = *(const float4*)(bias + j);
    s.x += bv.x; s.y += bv.y; s.z += bv.z; s.w += bv.w;
    ((float4*)out)[idx] = s;
}

// ---------------------------------------------------------------------------
extern "C" void kernel_launch(void* const* d_in, const int* in_sizes, int n_in,
                              void* d_out, int out_size) {
    const float* x      = (const float*)d_in[0];
    const float* W_attn = (const float*)d_in[1];
    const float* b_attn = (const float*)d_in[2];
    const float* W_proj = (const float*)d_in[3];
    const float* b_proj = (const float*)d_in[4];
    float* out = (float*)d_out;

    qkv_gemm<<<dim3(18, 8), 256>>>(x, W_attn, b_attn);
    sim_kernel<<<dim3(8, 8, 24), 256>>>();
    dpp_kernel<<<dim3(64, 24), 256>>>();
    proj_gemm<<<dim3(6, 8, 6), 256>>>(W_proj);
    proj_reduce<<<768, 256>>>(b_proj, out);
}

// round 17
// speedup vs baseline: 1.0037x; 1.0037x over previous
#include <cuda_runtime.h>
#include <math.h>

#define NC 36
#define WPB 8   // dpp tokens (warps) per block

// Scratch (no allocation allowed -> __device__ globals)
__device__ __align__(16) float g_q[24 * 512 * 64];
__device__ __align__(16) float g_k[24 * 512 * 64];
__device__ __align__(16) float g_v[24 * 512 * 64];
__device__ __align__(16) float g_sim[(size_t)24 * 512 * 512];
__device__ __align__(16) float g_ymid[1024 * 768];
__device__ __align__(16) float g_part[(size_t)6 * 1024 * 768];

// ---- packed f32x2 helpers (ptxas never emits FFMA2 from C++; PTX only) ----
__device__ __forceinline__ unsigned long long dup2(float x) {
    unsigned long long r;
    asm("mov.b64 %0, {%1, %1};" : "=l"(r) : "f"(x));
    return r;
}
__device__ __forceinline__ void fma2(unsigned long long& d,
                                     unsigned long long a,
                                     unsigned long long b) {
    asm("fma.rn.f32x2 %0, %1, %2, %0;" : "+l"(d) : "l"(a), "l"(b));
}
__device__ __forceinline__ float2 unpk(unsigned long long v) {
    float2 f;
    asm("mov.b64 {%0, %1}, %2;" : "=f"(f.x), "=f"(f.y) : "l"(v));
    return f;
}

// ---------------------------------------------------------------------------
// Kernel 1: qkv = x @ W_attn^T + b_attn, scattered into per-head q/k/v layout.
// 128x128 tile, BK=16, 256 threads, 8x8 micro-tile, double-buffered smem,
// packed fma.rn.f32x2 inner loop (2 FMA / fma-pipe slot).
// ---------------------------------------------------------------------------
__global__ __launch_bounds__(256, 2)
void qkv_gemm(const float* __restrict__ X, const float* __restrict__ W,
              const float* __restrict__ bias) {
    __shared__ float As[2][16][132];
    __shared__ float Bs[2][16][132];
    const int tid = threadIdx.x;
    const int tx = tid & 15, ty = tid >> 4;
    const int row0 = blockIdx.y * 128;
    const int col0 = blockIdx.x * 128;
    const int lr = tid >> 2;          // 0..63
    const int lk = (tid & 3) * 4;     // 0,4,8,12
    unsigned long long accp[8][4] = {};   // 8 rows x 4 col-pairs

    const float* pa0 = X + (size_t)(row0 + lr) * 768 + lk;
    const float* pa1 = X + (size_t)(row0 + lr + 64) * 768 + lk;
    const float* pb0 = W + (size_t)(col0 + lr) * 768 + lk;
    const float* pb1 = W + (size_t)(col0 + lr + 64) * 768 + lk;

    float4 fa0 = *(const float4*)pa0;
    float4 fa1 = *(const float4*)pa1;
    float4 fb0 = *(const float4*)pb0;
    float4 fb1 = *(const float4*)pb1;
    As[0][lk + 0][lr] = fa0.x; As[0][lk + 1][lr] = fa0.y;
    As[0][lk + 2][lr] = fa0.z; As[0][lk + 3][lr] = fa0.w;
    As[0][lk + 0][lr + 64] = fa1.x; As[0][lk + 1][lr + 64] = fa1.y;
    As[0][lk + 2][lr + 64] = fa1.z; As[0][lk + 3][lr + 64] = fa1.w;
    Bs[0][lk + 0][lr] = fb0.x; Bs[0][lk + 1][lr] = fb0.y;
    Bs[0][lk + 2][lr] = fb0.z; Bs[0][lk + 3][lr] = fb0.w;
    Bs[0][lk + 0][lr + 64] = fb1.x; Bs[0][lk + 1][lr + 64] = fb1.y;
    Bs[0][lk + 2][lr + 64] = fb1.z; Bs[0][lk + 3][lr + 64] = fb1.w;
    __syncthreads();

    const int NT = 768 / 16;
    for (int t = 0; t < NT; t++) {
        const int buf = t & 1;
        if (t < NT - 1) {
            int off = (t + 1) * 16;
            fa0 = *(const float4*)(pa0 + off);
            fa1 = *(const float4*)(pa1 + off);
            fb0 = *(const float4*)(pb0 + off);
            fb1 = *(const float4*)(pb1 + off);
        }
#pragma unroll
        for (int kk = 0; kk < 16; kk++) {
            float4 a0 = *(const float4*)&As[buf][kk][ty * 8];
            float4 a1 = *(const float4*)&As[buf][kk][ty * 8 + 4];
            ulonglong2 bl = *(const ulonglong2*)&Bs[buf][kk][tx * 8];
            ulonglong2 bh = *(const ulonglong2*)&Bs[buf][kk][tx * 8 + 4];
            unsigned long long bp0 = bl.x, bp1 = bl.y, bp2 = bh.x, bp3 = bh.y;
            float av[8] = {a0.x, a0.y, a0.z, a0.w, a1.x, a1.y, a1.z, a1.w};
#pragma unroll
            for (int r = 0; r < 8; r++) {
                unsigned long long ad = dup2(av[r]);
                fma2(accp[r][0], ad, bp0);
                fma2(accp[r][1], ad, bp1);
                fma2(accp[r][2], ad, bp2);
                fma2(accp[r][3], ad, bp3);
            }
        }
        if (t < NT - 1) {
            const int nb = buf ^ 1;
            As[nb][lk + 0][lr] = fa0.x; As[nb][lk + 1][lr] = fa0.y;
            As[nb][lk + 2][lr] = fa0.z; As[nb][lk + 3][lr] = fa0.w;
            As[nb][lk + 0][lr + 64] = fa1.x; As[nb][lk + 1][lr + 64] = fa1.y;
            As[nb][lk + 2][lr + 64] = fa1.z; As[nb][lk + 3][lr + 64] = fa1.w;
            Bs[nb][lk + 0][lr] = fb0.x; Bs[nb][lk + 1][lr] = fb0.y;
            Bs[nb][lk + 2][lr] = fb0.z; Bs[nb][lk + 3][lr] = fb0.w;
            Bs[nb][lk + 0][lr + 64] = fb1.x; Bs[nb][lk + 1][lr + 64] = fb1.y;
            Bs[nb][lk + 2][lr + 64] = fb1.z; Bs[nb][lk + 3][lr + 64] = fb1.w;
            __syncthreads();
        }
    }

    // Epilogue: bias + scatter into per-head q/k/v layout.
    const int j0 = col0 + tx * 8;
    float bb[8];
    *(float4*)&bb[0] = *(const float4*)(bias + j0);
    *(float4*)&bb[4] = *(const float4*)(bias + j0 + 4);
    const int which = j0 / 768;
    const int cc0 = j0 % 768;
    const int head = cc0 >> 6;
    const int d0 = cc0 & 63;
    float* dstbase = (which == 0) ? g_q : (which == 1) ? g_k : g_v;
#pragma unroll
    for (int r = 0; r < 8; r++) {
        int i = row0 + ty * 8 + r;
        int b_ = i >> 9, t = i & 511;
        int bh = b_ * 12 + head;
        float* p = dstbase + ((size_t)(bh * 512 + t)) * 64 + d0;
        float2 c0 = unpk(accp[r][0]), c1 = unpk(accp[r][1]);
        float2 c2 = unpk(accp[r][2]), c3 = unpk(accp[r][3]);
        *(float4*)p = make_float4(c0.x + bb[0], c0.y + bb[1],
                                  c1.x + bb[2], c1.y + bb[3]);
        *(float4*)(p + 4) = make_float4(c2.x + bb[4], c2.y + bb[5],
                                        c3.x + bb[6], c3.y + bb[7]);
    }
}

// ---------------------------------------------------------------------------
// Kernel 2: per-head similarity S[h][i][j] = q[h][i].k[h][j] (j<=i, else -inf)
// Transposed smem ([d][token]) so column pairs are contiguous -> f32x2.
// ---------------------------------------------------------------------------
__global__ void sim_kernel() {
    int h = blockIdx.z;
    int ti = blockIdx.y, tj = blockIdx.x;
    if (tj > ti) return;   // above-diagonal tiles never read
    __shared__ float Qs[64][68];   // [d][token], 68 stride keeps 16B align
    __shared__ float Ks[64][68];
    int tid = threadIdx.x;
    const int lr = tid >> 2;          // token 0..63
    const int lk = (tid & 3) * 4;     // d base 0,4,8,12
#pragma unroll
    for (int e = 0; e < 4; e++) {
        int d = lk + e * 16;
        float4 fq = *(const float4*)(g_q + ((size_t)(h * 512) + ti * 64 + lr) * 64 + d);
        Qs[d + 0][lr] = fq.x; Qs[d + 1][lr] = fq.y;
        Qs[d + 2][lr] = fq.z; Qs[d + 3][lr] = fq.w;
        float4 fk = *(const float4*)(g_k + ((size_t)(h * 512) + tj * 64 + lr) * 64 + d);
        Ks[d + 0][lr] = fk.x; Ks[d + 1][lr] = fk.y;
        Ks[d + 2][lr] = fk.z; Ks[d + 3][lr] = fk.w;
    }
    __syncthreads();
    int tx = tid & 15, ty = tid >> 4;
    unsigned long long accp[4][2] = {};
#pragma unroll 8
    for (int d = 0; d < 64; d++) {
        float4 a = *(const float4*)&Qs[d][ty * 4];
        ulonglong2 b = *(const ulonglong2*)&Ks[d][tx * 4];
        float av[4] = {a.x, a.y, a.z, a.w};
#pragma unroll
        for (int r = 0; r < 4; r++) {
            unsigned long long ad = dup2(av[r]);
            fma2(accp[r][0], ad, b.x);
            fma2(accp[r][1], ad, b.y);
        }
    }
#pragma unroll
    for (int r = 0; r < 4; r++) {
        int i = ti * 64 + ty * 4 + r;
        float2 c0 = unpk(accp[r][0]);
        float2 c1 = unpk(accp[r][1]);
        float vv[4] = {c0.x, c0.y, c1.x, c1.y};
#pragma unroll
        for (int c = 0; c < 4; c++) {
            int j = tj * 64 + tx * 4 + c;
            g_sim[((size_t)h * 512 + i) * 512 + j] = (j <= i) ? vv[c] : -INFINITY;
        }
    }
}

// ---------------------------------------------------------------------------
// Kernel 3: DPP, one WARP per (head, token). 8 tokens per block, no block
// barriers at all — everything is warp-local (__syncwarp / shuffles).
// ---------------------------------------------------------------------------
__global__ __launch_bounds__(256)
void dpp_kernel() {
    const int w    = threadIdx.x >> 5;           // warp slot = token slot
    const int lane = threadIdx.x & 31;
    const int i    = blockIdx.x * WPB + w;       // token 0..511
    const int bh   = blockIdx.y;                 // 0..23

    __shared__ float s_sim[WPB][512];
    __shared__ float kc[WPB][9][65];             // pad 65 -> conflict-free gram
    __shared__ float G[WPB][9][9];
    __shared__ float sc[WPB][NC];
    __shared__ float sw[WPB][NC][3];
    __shared__ unsigned char sg[WPB][NC][3];
    __shared__ float sprob[WPB][NC];
    __shared__ float coeff[WPB][9];
    __shared__ int   topidx[WPB][8];
    __shared__ float topval[WPB][8];

    const float* simrow = g_sim + ((size_t)bh * 512 + i) * 512;
#pragma unroll
    for (int e = 0; e < 16; e++) {
        int j = lane + e * 32;
        s_sim[w][j] = (j <= i) ? simrow[j] : -INFINITY;
    }
    __syncwarp();

    const float simi = s_sim[w][i];   // diagonal, always valid

    // ---- iterative top-8 argmax (tie -> lower index) ----
    for (int it = 0; it < 8; it++) {
        float bv = -INFINITY; int bi = 0x7fffffff;
#pragma unroll
        for (int e = 0; e < 16; e++) {
            int j = lane + e * 32;
            float v = s_sim[w][j];
            if (v > bv || (v == bv && j < bi)) { bv = v; bi = j; }
        }
#pragma unroll
        for (int off = 16; off > 0; off >>= 1) {
            float ov = __shfl_down_sync(0xffffffffu, bv, off);
            int   oi = __shfl_down_sync(0xffffffffu, bi, off);
            if (ov > bv || (ov == bv && oi < bi)) { bv = ov; bi = oi; }
        }
        bi = __shfl_sync(0xffffffffu, bi, 0);
        bv = __shfl_sync(0xffffffffu, bv, 0);
        if (lane == 0) { topidx[w][it] = bi; topval[w][it] = bv; }
        s_sim[w][bi] = -INFINITY;    // all lanes write same value
        __syncwarp();
    }

    const int n_cand = (i + 1 < 8) ? (i + 1) : 8;

    // ---- load 9 candidate k-vectors ----
    for (int idx = lane; idx < 9 * 64; idx += 32) {
        int m = idx >> 6, d = idx & 63;
        int src = (m == 0) ? i : topidx[w][m - 1];
        kc[w][m][d] = g_k[((size_t)bh * 512 + src) * 64 + d];
    }
    __syncwarp();

    // ---- 9x9 Gram (45 unique dots spread over lanes) ----
    for (int p = lane; p < 45; p += 32) {
        int a = 0, t = p;
        while (t >= 9 - a) { t -= 9 - a; a++; }
        int b = a + t;
        float dot = 0.f;
#pragma unroll 16
        for (int d = 0; d < 64; d++) dot = fmaf(kc[w][a][d], kc[w][b][d], dot);
        G[w][a][b] = dot;
        G[w][b][a] = dot;
    }
    __syncwarp();

    // ---- 36 combos: det, score, subset softmax weights ----
    for (int c = lane; c < NC; c += 32) {
        int s0, s1 = -1, n;
        if (c < 8) { s0 = c; n = 2; }
        else {
            int cc = c - 8, a = 0;
            while (cc >= 7 - a) { cc -= 7 - a; a++; }
            s0 = a; s1 = a + 1 + cc; n = 3;
        }
        bool valid = (s0 < n_cand) && (topidx[w][s0] != i);
        if (n == 3) valid = valid && (s1 < n_cand) && (topidx[w][s1] != i);

        int g1 = s0 + 1;
        int g2 = (n == 3) ? s1 + 1 : 0;
        float w0 = 0.f, w1 = 0.f, w2 = 0.f;
        float score = -INFINITY;
        if (valid) {
            float a00 = G[w][0][0], a01 = G[w][0][g1], a11 = G[w][g1][g1];
            float det;
            if (n == 2) {
                det = a00 * a11 - a01 * a01;
            } else {
                float a02 = G[w][0][g2], a12 = G[w][g1][g2], a22 = G[w][g2][g2];
                det = a00 * (a11 * a22 - a12 * a12)
                    - a01 * (a01 * a22 - a12 * a02)
                    + a02 * (a01 * a12 - a11 * a02);
            }
            score = logf(det + 1e-6f) / (float)n;
            float d0 = simi * 0.125f;
            float d1 = topval[w][s0] * 0.125f;
            float d2 = (n == 3) ? topval[w][s1] * 0.125f : -INFINITY;
            float m = fmaxf(d0, d1);
            if (n == 3) m = fmaxf(m, d2);
            float e0 = expf(d0 - m), e1 = expf(d1 - m);
            float e2 = (n == 3) ? expf(d2 - m) : 0.f;
            float inv = 1.f / (e0 + e1 + e2);
            w0 = e0 * inv; w1 = e1 * inv; w2 = e2 * inv;
        }
        sc[w][c] = score;
        sw[w][c][0] = w0; sw[w][c][1] = w1; sw[w][c][2] = w2;
        sg[w][c][0] = 0;
        sg[w][c][1] = (unsigned char)g1;
        sg[w][c][2] = (unsigned char)g2;
    }
    __syncwarp();

    // ---- softmax over 36 combo scores (lane 0 serial, then broadcast) ----
    float smax = -INFINITY, sinv = 0.f;
    int hv = 0;
    if (lane == 0) {
        for (int c = 0; c < NC; c++) smax = fmaxf(smax, sc[w][c]);
        hv = (smax > -INFINITY) ? 1 : 0;
        float sum = 0.f;
        if (hv) for (int c = 0; c < NC; c++) sum += expf(sc[w][c] - smax);
        sinv = (sum > 0.f) ? 1.f / sum : 0.f;
    }
    smax = __shfl_sync(0xffffffffu, smax, 0);
    sinv = __shfl_sync(0xffffffffu, sinv, 0);
    hv   = __shfl_sync(0xffffffffu, hv, 0);

    for (int c = lane; c < NC; c += 32)
        sprob[w][c] = hv ? expf(sc[w][c] - smax) * sinv : 0.f;
    __syncwarp();

    // ---- deterministic per-candidate coefficient reduction ----
    if (lane < 9) {
        float acc = 0.f;
        for (int c = 0; c < NC; c++) {
            float p = sprob[w][c];
            if (sg[w][c][0] == lane) acc = fmaf(p, sw[w][c][0], acc);
            if (sg[w][c][1] == lane) acc = fmaf(p, sw[w][c][1], acc);
            if (sg[w][c][2] == lane) acc = fmaf(p, sw[w][c][2], acc);
        }
        coeff[w][lane] = acc;
    }
    __syncwarp();

    // ---- output: y = sum_m coeff[m] * v[idx_m] (or v[i] if no valid combo) ----
    const float* vbase = g_v + (size_t)bh * 512 * 64;
    const int b_ = bh / 12, head = bh % 12;
#pragma unroll
    for (int e = 0; e < 2; e++) {
        int d = lane + e * 32;
        float y;
        if (hv) {
            y = coeff[w][0] * vbase[i * 64 + d];
#pragma unroll
            for (int m = 0; m < 8; m++)
                y = fmaf(coeff[w][m + 1], vbase[topidx[w][m] * 64 + d], y);
        } else {
            y = vbase[i * 64 + d];
        }
        g_ymid[((size_t)(b_ * 512 + i)) * 768 + head * 64 + d] = y;
    }
}

// ---------------------------------------------------------------------------
// Kernel 4: proj partial GEMM, split-K=6, double-buffered, f32x2 inner loop.
// grid (6, 8, 6) = 288 blocks.
// ---------------------------------------------------------------------------
__global__ __launch_bounds__(256, 2)
void proj_gemm(const float* __restrict__ W) {
    __shared__ float As[2][16][132];
    __shared__ float Bs[2][16][132];
    const int tid = threadIdx.x;
    const int tx = tid & 15, ty = tid >> 4;
    const int row0 = blockIdx.y * 128;
    const int col0 = blockIdx.x * 128;
    const int kbeg = blockIdx.z * 128;
    const int lr = tid >> 2;
    const int lk = (tid & 3) * 4;
    unsigned long long accp[8][4] = {};

    const float* pa0 = g_ymid + (size_t)(row0 + lr) * 768 + kbeg + lk;
    const float* pa1 = g_ymid + (size_t)(row0 + lr + 64) * 768 + kbeg + lk;
    const float* pb0 = W + (size_t)(col0 + lr) * 768 + kbeg + lk;
    const float* pb1 = W + (size_t)(col0 + lr + 64) * 768 + kbeg + lk;

    float4 fa0 = *(const float4*)pa0;
    float4 fa1 = *(const float4*)pa1;
    float4 fb0 = *(const float4*)pb0;
    float4 fb1 = *(const float4*)pb1;
    As[0][lk + 0][lr] = fa0.x; As[0][lk + 1][lr] = fa0.y;
    As[0][lk + 2][lr] = fa0.z; As[0][lk + 3][lr] = fa0.w;
    As[0][lk + 0][lr + 64] = fa1.x; As[0][lk + 1][lr + 64] = fa1.y;
    As[0][lk + 2][lr + 64] = fa1.z; As[0][lk + 3][lr + 64] = fa1.w;
    Bs[0][lk + 0][lr] = fb0.x; Bs[0][lk + 1][lr] = fb0.y;
    Bs[0][lk + 2][lr] = fb0.z; Bs[0][lk + 3][lr] = fb0.w;
    Bs[0][lk + 0][lr + 64] = fb1.x; Bs[0][lk + 1][lr + 64] = fb1.y;
    Bs[0][lk + 2][lr + 64] = fb1.z; Bs[0][lk + 3][lr + 64] = fb1.w;
    __syncthreads();

    const int NT = 8;   // 128 / 16
    for (int t = 0; t < NT; t++) {
        const int buf = t & 1;
        if (t < NT - 1) {
            int off = (t + 1) * 16;
            fa0 = *(const float4*)(pa0 + off);
            fa1 = *(const float4*)(pa1 + off);
            fb0 = *(const float4*)(pb0 + off);
            fb1 = *(const float4*)(pb1 + off);
        }
#pragma unroll
        for (int kk = 0; kk < 16; kk++) {
            float4 a0 = *(const float4*)&As[buf][kk][ty * 8];
            float4 a1 = *(const float4*)&As[buf][kk][ty * 8 + 4];
            ulonglong2 bl = *(const ulonglong2*)&Bs[buf][kk][tx * 8];
            ulonglong2 bh = *(const ulonglong2*)&Bs[buf][kk][tx * 8 + 4];
            unsigned long long bp0 = bl.x, bp1 = bl.y, bp2 = bh.x, bp3 = bh.y;
            float av[8] = {a0.x, a0.y, a0.z, a0.w, a1.x, a1.y, a1.z, a1.w};
#pragma unroll
            for (int r = 0; r < 8; r++) {
                unsigned long long ad = dup2(av[r]);
                fma2(accp[r][0], ad, bp0);
                fma2(accp[r][1], ad, bp1);
                fma2(accp[r][2], ad, bp2);
                fma2(accp[r][3], ad, bp3);
            }
        }
        if (t < NT - 1) {
            const int nb = buf ^ 1;
            As[nb][lk + 0][lr] = fa0.x; As[nb][lk + 1][lr] = fa0.y;
            As[nb][lk + 2][lr] = fa0.z; As[nb][lk + 3][lr] = fa0.w;
            As[nb][lk + 0][lr + 64] = fa1.x; As[nb][lk + 1][lr + 64] = fa1.y;
            As[nb][lk + 2][lr + 64] = fa1.z; As[nb][lk + 3][lr + 64] = fa1.w;
            Bs[nb][lk + 0][lr] = fb0.x; Bs[nb][lk + 1][lr] = fb0.y;
            Bs[nb][lk + 2][lr] = fb0.z; Bs[nb][lk + 3][lr] = fb0.w;
            Bs[nb][lk + 0][lr + 64] = fb1.x; Bs[nb][lk + 1][lr + 64] = fb1.y;
            Bs[nb][lk + 2][lr + 64] = fb1.z; Bs[nb][lk + 3][lr + 64] = fb1.w;
            __syncthreads();
        }
    }

    float* part = g_part + (size_t)blockIdx.z * (1024 * 768);
    const int j0 = col0 + tx * 8;
#pragma unroll
    for (int r = 0; r < 8; r++) {
        int i = row0 + ty * 8 + r;
        float* p = part + (size_t)i * 768 + j0;
        float2 c0 = unpk(accp[r][0]), c1 = unpk(accp[r][1]);
        float2 c2 = unpk(accp[r][2]), c3 = unpk(accp[r][3]);
        *(float4*)p       = make_float4(c0.x, c0.y, c1.x, c1.y);
        *(float4*)(p + 4) = make_float4(c2.x, c2.y, c3.x, c3.y);
    }
}

// ---------------------------------------------------------------------------
// Kernel 5: reduce split-K partials + bias (deterministic fixed order).
// ---------------------------------------------------------------------------
__global__ void proj_reduce(const float* __restrict__ bias, float* __restrict__ out) {
    const int idx = blockIdx.x * 256 + threadIdx.x;   // float4 index, 196608 total
    const float4* p = (const float4*)g_part;
    float4 s = p[idx];
#pragma unroll
    for (int z = 1; z < 6; z++) {
        float4 t = p[idx + z * 196608];
        s.x += t.x; s.y += t.y; s.z += t.z; s.w += t.w;
    }
    int j = (idx * 4) % 768;
    float4 bv = *(const float4*)(bias + j);
    s.x += bv.x; s.y += bv.y; s.z += bv.z; s.w += bv.w;
    ((float4*)out)[idx] = s;
}

// ---------------------------------------------------------------------------
extern "C" void kernel_launch(void* const* d_in, const int* in_sizes, int n_in,
                              void* d_out, int out_size) {
    const float* x      = (const float*)d_in[0];
    const float* W_attn = (const float*)d_in[1];
    const float* b_attn = (const float*)d_in[2];
    const float* W_proj = (const float*)d_in[3];
    const float* b_proj = (const float*)d_in[4];
    float* out = (float*)d_out;

    qkv_gemm<<<dim3(18, 8), 256>>>(x, W_attn, b_attn);
    sim_kernel<<<dim3(8, 8, 24), 256>>>();
    dpp_kernel<<<dim3(64, 24), 256>>>();
    proj_gemm<<<dim3(6, 8, 6), 256>>>(W_proj);
    proj_reduce<<<768, 256>>>(b_proj, out);
}